// round 2
// baseline (speedup 1.0000x reference)
#include <cuda_runtime.h>
#include <math.h>

#define D_MODEL 512
#define D_HID   1024
#define NTOK    4096
#define NEXP    64
#define TOPK    8
#define CAPV    1024
#define NNULL   64

// ---------------- scratch (static device globals; no allocation) ----------------
__device__ int   g_cnt[NEXP];
__device__ int   g_tok[NEXP*CAPV];
__device__ float g_wgt[NEXP*CAPV];
__device__ int   g_slot[NTOK*TOPK];
__device__ float g_Psum[NEXP];
__device__ float g_lse2;
__device__ int   g_null;
__device__ float g_hs[(size_t)NTOK*D_HID];               // shared-expert hidden  (16 MB)
__device__ float g_he[(size_t)NEXP*CAPV*D_HID];          // routed hidden        (268 MB)
__device__ float g_oexp[(size_t)NEXP*CAPV*D_MODEL];      // routed per-slot out  (134 MB)

__global__ void k_zero() {
  int i = threadIdx.x;
  if (i < NEXP) { g_cnt[i] = 0; g_Psum[i] = 0.f; }
  if (i == NEXP)   g_lse2 = 0.f;
  if (i == NEXP+1) g_null = 0;
}

// ---------------- router: logits, top-k (JAX tie-break), dispatch, aux stats ----
__global__ __launch_bounds__(128) void k_router(const float* __restrict__ x,
                                                const float* __restrict__ gw,
                                                const float* __restrict__ bias,
                                                const float* __restrict__ nullp) {
  __shared__ float xs[D_MODEL];
  __shared__ float lg[NEXP];
  int t = blockIdx.x, tid = threadIdx.x;
  *(float4*)(xs + tid*4) = *(const float4*)(x + (size_t)t*D_MODEL + tid*4);
  __syncthreads();
  if (tid < NEXP) {
    const float* w = gw + (size_t)tid*D_MODEL;
    float s = 0.f;
    #pragma unroll 8
    for (int k = 0; k < D_MODEL; k += 4) {
      float4 wv = *(const float4*)(w + k);
      s += xs[k]*wv.x + xs[k+1]*wv.y + xs[k+2]*wv.z + xs[k+3]*wv.w;
    }
    lg[tid] = s + bias[tid];
  }
  __syncthreads();
  if (tid == 0) {
    float nv = *nullp;
    unsigned long long used = 0ull;
    int   sel[TOPK]; float sl[TOPK];
    int nnull = 0;
    // top-k over [real(0..63), null(64..127)]: softmax is monotone so ranking
    // logits == ranking probs; ties: lowest index first -> strict '>' scan,
    // and a null only wins on a strictly larger value (null indices are higher).
    for (int j = 0; j < TOPK; j++) {
      float best = -1e30f; int bi = -1;
      for (int e = 0; e < NEXP; e++)
        if (!((used >> e) & 1ull) && lg[e] > best) { best = lg[e]; bi = e; }
      if (nv > best) { sel[j] = -1; sl[j] = nv; nnull++; }
      else           { sel[j] = bi; sl[j] = best; used |= (1ull << bi); }
    }
    // renormalized weights == softmax over selected real logits
    float m = -1e30f;
    for (int j = 0; j < TOPK; j++) if (sel[j] >= 0 && sl[j] > m) m = sl[j];
    float wj[TOPK]; float ssum = 0.f;
    for (int j = 0; j < TOPK; j++) {
      wj[j] = (sel[j] >= 0) ? __expf(sl[j] - m) : 0.f;
      ssum += wj[j];
    }
    float inv = (ssum > 1e-30f) ? 1.f/ssum : 0.f;
    for (int j = 0; j < TOPK; j++) {
      int slot = -1;
      if (sel[j] >= 0) {
        int pos = atomicAdd(&g_cnt[sel[j]], 1);   // counts ALL real picks (aux f_real)
        if (pos < CAPV) {
          slot = sel[j]*CAPV + pos;
          g_tok[slot] = t;
          g_wgt[slot] = wj[j]*inv;
        }
      }
      g_slot[t*TOPK + j] = slot;                  // -1: null or capacity-dropped
    }
    if (nnull) atomicAdd(&g_null, nnull);
    // aux stats: P_real (softmax over 64 real), lse over all 128 logits
    float mr = -1e30f;
    for (int e = 0; e < NEXP; e++) if (lg[e] > mr) mr = lg[e];
    float Z = 0.f;
    for (int e = 0; e < NEXP; e++) Z += __expf(lg[e]-mr);
    float invZ = 1.f/Z;
    for (int e = 0; e < NEXP; e++) atomicAdd(&g_Psum[e], __expf(lg[e]-mr)*invZ);
    float m2 = fmaxf(mr, nv);
    float Z2 = Z*__expf(mr-m2) + (float)NNULL*__expf(nv-m2);
    float lse = m2 + logf(Z2);
    atomicAdd(&g_lse2, lse*lse);
  }
}

// ---------------- tiled fp32 GEMM building blocks -------------------------------
// B tile into smem [16][132]; BT=false: B is [K,N] (NN); BT=true: B is [N,K] (NT).
template<bool BT>
__device__ __forceinline__ void load_btile(const float* __restrict__ B, int ldb,
                                           int k0, int n0, float* Bs, int tid) {
  if (!BT) {
    #pragma unroll
    for (int r = 0; r < 2; r++) {
      int idx = tid + r*256;
      int kk = idx >> 5, jq = idx & 31;
      float4 v = *(const float4*)(B + (size_t)(k0+kk)*ldb + n0 + jq*4);
      *(float4*)(Bs + kk*132 + jq*4) = v;
    }
  } else {
    #pragma unroll
    for (int r = 0; r < 2; r++) {
      int idx = tid + r*256;
      int j = idx >> 2, kq = idx & 3;
      float4 v = *(const float4*)(B + (size_t)(n0+j)*ldb + k0 + kq*4);
      Bs[(kq*4+0)*132 + j] = v.x;
      Bs[(kq*4+1)*132 + j] = v.y;
      Bs[(kq*4+2)*132 + j] = v.z;
      Bs[(kq*4+3)*132 + j] = v.w;
    }
  }
}

__device__ __forceinline__ float siluf(float v) { return v/(1.f + __expf(-v)); }

// Dual GEMM: h = silu(A@W0) * (A@W1). 64x128 tile, K=512.
// GATHER=false: A = x rows (shared expert, B layout NT: W[H,D]) -> g_hs
// GATHER=true : A = gathered token rows per expert (B layout NN: W[D,H]) -> g_he
template<bool GATHER, bool BT>
__global__ __launch_bounds__(256) void k_gateup(const float* __restrict__ X,
                                                const float* __restrict__ W0,
                                                const float* __restrict__ W1) {
  __shared__ __align__(16) float As[64*16];
  __shared__ __align__(16) float Bs0[16*132];
  __shared__ __align__(16) float Bs1[16*132];
  __shared__ int toks[64];
  const int ldb = BT ? D_MODEL : D_HID;
  int m0 = blockIdx.x*64, n0 = blockIdx.y*128;
  int e = GATHER ? blockIdx.z : 0;
  int tid = threadIdx.x;
  int cnt = 0;
  const float* B0 = W0; const float* B1 = W1;
  if (GATHER) {
    cnt = min(g_cnt[e], CAPV);
    if (m0 >= cnt) return;
    B0 += (size_t)e*D_MODEL*D_HID;
    B1 += (size_t)e*D_MODEL*D_HID;
    if (tid < 64) toks[tid] = (m0+tid < cnt) ? g_tok[e*CAPV + m0 + tid] : -1;
    __syncthreads();
  }
  int arow = tid >> 2, akq = tid & 3;
  const float* Arow;
  if (GATHER) {
    int tk = toks[arow];
    Arow = (tk >= 0) ? (X + (size_t)tk*D_MODEL) : (const float*)0;
  } else {
    Arow = X + (size_t)(m0+arow)*D_MODEL;
  }
  float acc0[8][4] = {}; float acc1[8][4] = {};
  int r0 = (tid>>5)*8, c0 = (tid&31)*4;
  for (int k0 = 0; k0 < D_MODEL; k0 += 16) {
    __syncthreads();
    float4 av = make_float4(0.f,0.f,0.f,0.f);
    if (Arow) av = *(const float4*)(Arow + k0 + akq*4);
    *(float4*)(As + arow*16 + akq*4) = av;
    load_btile<BT>(B0, ldb, k0, n0, Bs0, tid);
    load_btile<BT>(B1, ldb, k0, n0, Bs1, tid);
    __syncthreads();
    #pragma unroll
    for (int kk = 0; kk < 16; kk++) {
      float4 b0 = *(const float4*)(Bs0 + kk*132 + c0);
      float4 b1 = *(const float4*)(Bs1 + kk*132 + c0);
      #pragma unroll
      for (int i = 0; i < 8; i++) {
        float a = As[(r0+i)*16 + kk];      // warp-uniform -> smem broadcast
        acc0[i][0] += a*b0.x; acc0[i][1] += a*b0.y;
        acc0[i][2] += a*b0.z; acc0[i][3] += a*b0.w;
        acc1[i][0] += a*b1.x; acc1[i][1] += a*b1.y;
        acc1[i][2] += a*b1.z; acc1[i][3] += a*b1.w;
      }
    }
  }
  #pragma unroll
  for (int i = 0; i < 8; i++) {
    int m = m0 + r0 + i;
    if (GATHER && m >= cnt) continue;
    float4 h;
    h.x = siluf(acc0[i][0])*acc1[i][0];
    h.y = siluf(acc0[i][1])*acc1[i][1];
    h.z = siluf(acc0[i][2])*acc1[i][2];
    h.w = siluf(acc0[i][3])*acc1[i][3];
    float* dst = GATHER ? (g_he + ((size_t)e*CAPV + m)*D_HID + n0 + c0)
                        : (g_hs + (size_t)m*D_HID + n0 + c0);
    *(float4*)dst = h;
  }
}

// Down GEMM: out = H @ Wdown. 64x128 tile, K=1024.
// EXPERT=false: g_hs @ Wsd^T (NT, Wsd[D,H]) -> d_out (plain store)
// EXPERT=true : g_he @ W_down[e] (NN, [H,D]) * routing weight -> g_oexp
template<bool EXPERT, bool BT>
__global__ __launch_bounds__(256) void k_down(const float* __restrict__ W,
                                              float* __restrict__ Out) {
  __shared__ __align__(16) float As[64*16];
  __shared__ __align__(16) float Bs[16*132];
  const int ldb = BT ? D_HID : D_MODEL;
  int m0 = blockIdx.x*64, n0 = blockIdx.y*128;
  int e = EXPERT ? blockIdx.z : 0;
  int tid = threadIdx.x;
  int cnt = 0;
  const float* B = W;
  const float* Hin;
  if (EXPERT) {
    cnt = min(g_cnt[e], CAPV);
    if (m0 >= cnt) return;
    B += (size_t)e*D_HID*D_MODEL;
    Hin = g_he + ((size_t)e*CAPV + m0)*D_HID;
  } else {
    Hin = g_hs + (size_t)m0*D_HID;
  }
  int arow = tid >> 2, akq = tid & 3;
  float acc[8][4] = {};
  int r0 = (tid>>5)*8, c0 = (tid&31)*4;
  for (int k0 = 0; k0 < D_HID; k0 += 16) {
    __syncthreads();
    float4 av = *(const float4*)(Hin + (size_t)arow*D_HID + k0 + akq*4);
    *(float4*)(As + arow*16 + akq*4) = av;
    load_btile<BT>(B, ldb, k0, n0, Bs, tid);
    __syncthreads();
    #pragma unroll
    for (int kk = 0; kk < 16; kk++) {
      float4 b = *(const float4*)(Bs + kk*132 + c0);
      #pragma unroll
      for (int i = 0; i < 8; i++) {
        float a = As[(r0+i)*16 + kk];
        acc[i][0] += a*b.x; acc[i][1] += a*b.y;
        acc[i][2] += a*b.z; acc[i][3] += a*b.w;
      }
    }
  }
  #pragma unroll
  for (int i = 0; i < 8; i++) {
    int m = m0 + r0 + i;
    if (EXPERT) {
      if (m >= cnt) continue;
      float w = g_wgt[e*CAPV + m];
      float4 v;
      v.x = acc[i][0]*w; v.y = acc[i][1]*w; v.z = acc[i][2]*w; v.w = acc[i][3]*w;
      *(float4*)(g_oexp + ((size_t)e*CAPV + m)*D_MODEL + n0 + c0) = v;
    } else {
      float4 v;
      v.x = acc[i][0]; v.y = acc[i][1]; v.z = acc[i][2]; v.w = acc[i][3];
      *(float4*)(Out + (size_t)m*D_MODEL + n0 + c0) = v;
    }
  }
}

// ---------------- deterministic combine: out[t] = shared + sum_k oexp[slot] ----
__global__ __launch_bounds__(128) void k_combine(float* __restrict__ Out) {
  __shared__ int sl[TOPK];
  int t = blockIdx.x, tid = threadIdx.x;
  if (tid < TOPK) sl[tid] = g_slot[t*TOPK + tid];
  __syncthreads();
  size_t base = (size_t)t*D_MODEL + tid*4;
  float4 s = *(float4*)(Out + base);
  #pragma unroll
  for (int j = 0; j < TOPK; j++) {
    int S = sl[j];
    if (S >= 0) {
      float4 v = *(const float4*)(g_oexp + (size_t)S*D_MODEL + tid*4);
      s.x += v.x; s.y += v.y; s.z += v.z; s.w += v.w;
    }
  }
  *(float4*)(Out + base) = s;
}

// ---------------- aux loss scalar (guarded against short out buffers) -----------
__global__ void k_aux(float* __restrict__ Out, int out_size) {
  if (out_size <= NTOK*D_MODEL) return;   // no room for the aux scalar
  float sc = 0.f;
  for (int e = 0; e < NEXP; e++) sc += (float)g_cnt[e];
  float denom = fmaxf(sc, 1e-6f);
  float dot = 0.f;
  for (int e = 0; e < NEXP; e++)
    dot += ((float)g_cnt[e]/denom) * (g_Psum[e]/(float)NTOK);
  float Lbal = (float)NEXP * dot;
  float Lz = g_lse2 / (float)NTOK;
  float nr = (float)g_null / (float)(NTOK*TOPK);
  float d = nr - 0.5f;
  Out[(size_t)NTOK*D_MODEL] = 0.02f*Lbal + 0.001f*Lz + 0.01f*d*d;
}

// ---------------- launch --------------------------------------------------------
extern "C" void kernel_launch(void* const* d_in, const int* in_sizes, int n_in,
                              void* d_out, int out_size) {
  const float* x     = (const float*)d_in[0];
  const float* gw    = (const float*)d_in[1];
  const float* bias  = (const float*)d_in[2];
  const float* nullp = (const float*)d_in[3];
  const float* Wg    = (const float*)d_in[4];
  const float* Wu    = (const float*)d_in[5];
  const float* Wd    = (const float*)d_in[6];
  const float* Wsg   = (const float*)d_in[7];
  const float* Wsu   = (const float*)d_in[8];
  const float* Wsd   = (const float*)d_in[9];
  float* out = (float*)d_out;

  k_zero<<<1, 128>>>();
  k_router<<<NTOK, 128>>>(x, gw, bias, nullp);
  // shared expert
  k_gateup<false, true><<<dim3(NTOK/64, D_HID/128), 256>>>(x, Wsg, Wsu);
  k_down<false, true><<<dim3(NTOK/64, D_MODEL/128), 256>>>(Wsd, out);
  // routed experts
  k_gateup<true, false><<<dim3(CAPV/64, D_HID/128, NEXP), 256>>>(x, Wg, Wu);
  k_down<true, false><<<dim3(CAPV/64, D_MODEL/128, NEXP), 256>>>(Wd, out);
  // combine + aux
  k_combine<<<NTOK, 128>>>(out);
  k_aux<<<1, 1>>>(out, out_size);
}